// round 1
// baseline (speedup 1.0000x reference)
#include <cuda_runtime.h>
#include <cuda_bf16.h>
#include <cstdint>

#define NPIX 12544          // 112*112 (= 98 * 128)
#define NCH  768
#define EPSF 1e-8f

#define BM 128
#define BN 128
#define BK 32
#define LDS_PAD 40          // bf16 elements per shared row (80B stride -> conflict-free ldmatrix)

// ---------------- scratch (no allocations allowed) ----------------
__device__ __nv_bfloat16 g_Xt[(size_t)NPIX * NCH];   // [pixel][channel] bf16
__device__ __nv_bfloat16 g_St[(size_t)NPIX * NCH];
__device__ float g_sx[NPIX];                          // sum x^2 per pixel
__device__ float g_ss[NPIX];                          // sum s^2 per pixel
__device__ float g_inv_bn[NPIX];                      // 1/(sqrt(ss+eps)+eps)
__device__ unsigned long long g_best[NPIX];           // packed (sortable val, ~j)
__device__ float g_loss[NPIX];

// ---------------- transpose + fp32 -> bf16 convert ----------------
__global__ void k_transpose(const float* __restrict__ src, int dst_sel) {
    __shared__ float tile[32][33];
    __nv_bfloat16* dst = dst_sel ? g_St : g_Xt;
    int i0 = blockIdx.x * 32;
    int c0 = blockIdx.y * 32;
    tile[threadIdx.y][threadIdx.x] =
        src[(size_t)(c0 + threadIdx.y) * NPIX + i0 + threadIdx.x];
    __syncthreads();
    dst[(size_t)(i0 + threadIdx.y) * NCH + c0 + threadIdx.x] =
        __float2bfloat16(tile[threadIdx.x][threadIdx.y]);
}

// ---------------- per-pixel norms (exact fp32 from originals) ----------------
__global__ void k_norms(const float* __restrict__ x, const float* __restrict__ s) {
    int i = blockIdx.x * 256 + threadIdx.x;
    if (i >= NPIX) return;
    float sx = 0.f, ss = 0.f;
    for (int c = 0; c < NCH; c++) {
        float a = x[(size_t)c * NPIX + i]; sx += a * a;
        float b = s[(size_t)c * NPIX + i]; ss += b * b;
    }
    g_sx[i] = sx;
    g_ss[i] = ss;
    g_inv_bn[i] = 1.0f / (sqrtf(ss + EPSF) + EPSF);
    g_best[i] = 0ull;  // minimum packed value
}

// ---------------- GEMM (bf16 mma.sync) + fused per-row argmax ----------------
__global__ __launch_bounds__(256) void k_gemm_argmax() {
    __shared__ __nv_bfloat16 As[BM * LDS_PAD];
    __shared__ __nv_bfloat16 Bs[BN * LDS_PAD];

    const int i0 = blockIdx.y * BM;   // row tile (x pixels)
    const int j0 = blockIdx.x * BN;   // col tile (s pixels)
    const int t    = threadIdx.x;
    const int lane = t & 31;
    const int warp = t >> 5;
    const int wm = warp >> 2;         // 0..1  -> 64-row slice
    const int wn = warp & 3;          // 0..3  -> 32-col slice

    float acc[4][4][4];
    #pragma unroll
    for (int a = 0; a < 4; a++)
        #pragma unroll
        for (int b = 0; b < 4; b++)
            #pragma unroll
            for (int e = 0; e < 4; e++) acc[a][b][e] = 0.f;

    // ldmatrix lane addressing
    const int a_lrow = lane & 15;            // rows 0..15 of the 16x16 A tile
    const int a_lcol = (lane >> 4) << 3;     // lanes 16..31 -> k+8
    const int b_lane = lane & 15;
    const int b_lrow = b_lane & 7;           // n row within 8
    const int b_lcol = (b_lane >> 3) << 3;   // lanes 8..15 -> k+8

    for (int k0 = 0; k0 < NCH; k0 += BK) {
        // stage tiles: 128 rows x 32 k each, 16B chunks, 2 chunks/thread/tile
        #pragma unroll
        for (int u = 0; u < 2; u++) {
            int chunk = t + u * 256;         // 0..511
            int row = chunk >> 2;
            int kc  = (chunk & 3) << 3;
            *(uint4*)&As[row * LDS_PAD + kc] =
                *(const uint4*)&g_Xt[(size_t)(i0 + row) * NCH + k0 + kc];
            *(uint4*)&Bs[row * LDS_PAD + kc] =
                *(const uint4*)&g_St[(size_t)(j0 + row) * NCH + k0 + kc];
        }
        __syncthreads();

        #pragma unroll
        for (int kk = 0; kk < 2; kk++) {
            uint32_t af[4][4];
            #pragma unroll
            for (int mt = 0; mt < 4; mt++) {
                uint32_t addr = (uint32_t)__cvta_generic_to_shared(
                    &As[(wm * 64 + mt * 16 + a_lrow) * LDS_PAD + kk * 16 + a_lcol]);
                asm volatile(
                    "ldmatrix.sync.aligned.m8n8.x4.shared.b16 {%0,%1,%2,%3}, [%4];"
                    : "=r"(af[mt][0]), "=r"(af[mt][1]), "=r"(af[mt][2]), "=r"(af[mt][3])
                    : "r"(addr));
            }
            uint32_t bfr[4][2];
            #pragma unroll
            for (int nt = 0; nt < 4; nt++) {
                uint32_t addr = (uint32_t)__cvta_generic_to_shared(
                    &Bs[(wn * 32 + nt * 8 + b_lrow) * LDS_PAD + kk * 16 + b_lcol]);
                asm volatile(
                    "ldmatrix.sync.aligned.m8n8.x2.shared.b16 {%0,%1}, [%2];"
                    : "=r"(bfr[nt][0]), "=r"(bfr[nt][1])
                    : "r"(addr));
            }
            #pragma unroll
            for (int mt = 0; mt < 4; mt++)
                #pragma unroll
                for (int nt = 0; nt < 4; nt++)
                    asm volatile(
                        "mma.sync.aligned.m16n8k16.row.col.f32.bf16.bf16.f32 "
                        "{%0,%1,%2,%3}, {%4,%5,%6,%7}, {%8,%9}, {%0,%1,%2,%3};"
                        : "+f"(acc[mt][nt][0]), "+f"(acc[mt][nt][1]),
                          "+f"(acc[mt][nt][2]), "+f"(acc[mt][nt][3])
                        : "r"(af[mt][0]), "r"(af[mt][1]), "r"(af[mt][2]), "r"(af[mt][3]),
                          "r"(bfr[nt][0]), "r"(bfr[nt][1]));
        }
        __syncthreads();
    }

    // ---- epilogue: scale by inv_bn[j], per-row argmax, atomic merge ----
    float ibn[4][2];
    #pragma unroll
    for (int nt = 0; nt < 4; nt++) {
        int j = j0 + wn * 32 + nt * 8 + (lane & 3) * 2;
        ibn[nt][0] = g_inv_bn[j];
        ibn[nt][1] = g_inv_bn[j + 1];
    }

    #pragma unroll
    for (int mt = 0; mt < 4; mt++) {
        #pragma unroll
        for (int rh = 0; rh < 2; rh++) {
            int row = i0 + wm * 64 + mt * 16 + rh * 8 + (lane >> 2);
            float bv = -3.4e38f;
            int   bj = 0;
            #pragma unroll
            for (int nt = 0; nt < 4; nt++) {
                #pragma unroll
                for (int e = 0; e < 2; e++) {
                    float v = acc[mt][nt][rh * 2 + e] * ibn[nt][e];
                    int j = j0 + wn * 32 + nt * 8 + (lane & 3) * 2 + e;
                    if (v > bv) { bv = v; bj = j; }   // ascending j scan: ties keep smallest j
                }
            }
            // reduce across the 4 lanes of the quad (same row, different cols)
            #pragma unroll
            for (int o = 1; o < 4; o <<= 1) {
                float ov = __shfl_xor_sync(0xffffffffu, bv, o);
                int   oj = __shfl_xor_sync(0xffffffffu, bj, o);
                if (ov > bv || (ov == bv && oj < bj)) { bv = ov; bj = oj; }
            }
            if ((lane & 3) == 0) {
                unsigned int u = __float_as_uint(bv);
                u = (u & 0x80000000u) ? ~u : (u | 0x80000000u);   // sortable float
                unsigned long long p =
                    ((unsigned long long)u << 32) | (unsigned int)(~(unsigned)bj);
                atomicMax(&g_best[row], p);   // ties -> larger ~j -> smaller j (argmin-first)
            }
        }
    }
}

// ---------------- exact fp32 cos loss on selected columns ----------------
__global__ void k_cos(const float* __restrict__ x, const float* __restrict__ s) {
    int i = blockIdx.x * 256 + threadIdx.x;
    if (i >= NPIX) return;
    unsigned long long p = g_best[i];
    int j = (int)(~(unsigned int)(p & 0xFFFFFFFFull));
    float dot = 0.f;
    for (int c = 0; c < NCH; c++)
        dot += x[(size_t)c * NPIX + i] * s[(size_t)c * NPIX + j];
    float cs = dot / ((sqrtf(g_sx[i]) + EPSF) * (sqrtf(g_ss[j]) + EPSF));
    g_loss[i] = 1.0f - cs;
}

// ---------------- deterministic final reduction ----------------
__global__ void k_reduce(float* __restrict__ out) {
    __shared__ float sm[256];
    float sum = 0.f;
    for (int i = threadIdx.x; i < NPIX; i += 256) sum += g_loss[i];
    sm[threadIdx.x] = sum;
    __syncthreads();
    for (int o = 128; o > 0; o >>= 1) {
        if (threadIdx.x < o) sm[threadIdx.x] += sm[threadIdx.x + o];
        __syncthreads();
    }
    if (threadIdx.x == 0) out[0] = sm[0] / (float)NPIX;
}

// ---------------- launch ----------------
extern "C" void kernel_launch(void* const* d_in, const int* in_sizes, int n_in,
                              void* d_out, int out_size) {
    const float* x = (const float*)d_in[0];   // x_feats (1,768,112,112)
    const float* s = (const float*)d_in[1];   // s_feats
    float* out = (float*)d_out;

    dim3 tb(32, 32);
    dim3 tg(NPIX / 32, NCH / 32);
    k_transpose<<<tg, tb>>>(x, 0);
    k_transpose<<<tg, tb>>>(s, 1);
    k_norms<<<NPIX / 256, 256>>>(x, s);
    k_gemm_argmax<<<dim3(NPIX / BN, NPIX / BM), 256>>>();
    k_cos<<<NPIX / 256, 256>>>(x, s);
    k_reduce<<<1, 256>>>(out);
}

// round 3
// speedup vs baseline: 1.2169x; 1.2169x over previous
#include <cuda_runtime.h>
#include <cuda_bf16.h>
#include <cstdint>

#define NPIX 12544          // 112*112 = 98*128 = 49*256
#define NCH  768
#define EPSF 1e-8f

// ---- GEMM tile config (legacy mma.sync path; tcgen05 not reachable on compute_103) ----
#define BM 128
#define BN 256
#define BK 32
#define KT (NCH / BK)       // 24 k-tiles
#define NSTAGES 3
#define PAD 40              // bf16 elems per smem row (80B pitch -> conflict-free ldmatrix)

#define A_ROWS BM
#define B_ROWS BN
#define A_STAGE_ELE (A_ROWS * PAD)
#define B_STAGE_ELE (B_ROWS * PAD)
#define STAGE_ELE   (A_STAGE_ELE + B_STAGE_ELE)
#define STAGE_BYTES (STAGE_ELE * 2)                  // 30720
#define SMEM_TOTAL  (NSTAGES * STAGE_BYTES)          // 92160

// ---------------- scratch (no allocations allowed) ----------------
__device__ __nv_bfloat16 g_Xt[(size_t)NPIX * NCH];   // [pixel][channel] bf16
__device__ __nv_bfloat16 g_St[(size_t)NPIX * NCH];
__device__ float g_sx[NPIX];
__device__ float g_ss[NPIX];
__device__ float g_inv_bn[NPIX];
__device__ unsigned long long g_best[NPIX];
__device__ float g_loss[NPIX];

// ---------------- transpose + fp32 -> bf16 convert ----------------
__global__ void k_transpose(const float* __restrict__ src, int dst_sel) {
    __shared__ float tile[32][33];
    __nv_bfloat16* dst = dst_sel ? g_St : g_Xt;
    int i0 = blockIdx.x * 32;
    int c0 = blockIdx.y * 32;
    tile[threadIdx.y][threadIdx.x] =
        src[(size_t)(c0 + threadIdx.y) * NPIX + i0 + threadIdx.x];
    __syncthreads();
    dst[(size_t)(i0 + threadIdx.y) * NCH + c0 + threadIdx.x] =
        __float2bfloat16(tile[threadIdx.x][threadIdx.y]);
}

// ---------------- per-pixel norms (exact fp32 from originals, coalesced) ----------------
__global__ void k_norms(const float* __restrict__ x, const float* __restrict__ s) {
    int i = blockIdx.x * 256 + threadIdx.x;
    if (i >= NPIX) return;
    float sx = 0.f, ss = 0.f;
    for (int c = 0; c < NCH; c++) {
        float a = x[(size_t)c * NPIX + i]; sx += a * a;
        float b = s[(size_t)c * NPIX + i]; ss += b * b;
    }
    g_sx[i] = sx;
    g_ss[i] = ss;
    g_inv_bn[i] = 1.0f / (sqrtf(ss + EPSF) + EPSF);
    g_best[i] = 0ull;
}

// ---------------- GEMM (mma.sync bf16, cp.async pipeline) + fused argmax ----------------
__device__ __forceinline__ void load_stage(char* smem, int stage, int k0,
                                           int i0, int j0, int t) {
    __nv_bfloat16* As = (__nv_bfloat16*)(smem + stage * STAGE_BYTES);
    __nv_bfloat16* Bs = As + A_STAGE_ELE;
    #pragma unroll
    for (int u = 0; u < 6; u++) {
        int chunk = t + u * 256;                 // 0..1535 (16B chunks)
        if (chunk < 512) {                       // A: 128 rows x 4 chunks
            int row = chunk >> 2, sub = chunk & 3;
            uint32_t dst = (uint32_t)__cvta_generic_to_shared(
                &As[row * PAD + sub * 8]);
            const void* src = &g_Xt[(size_t)(i0 + row) * NCH + k0 + sub * 8];
            asm volatile("cp.async.cg.shared.global [%0], [%1], 16;"
                         :: "r"(dst), "l"(src));
        } else {                                 // B: 256 rows x 4 chunks
            int c = chunk - 512;
            int row = c >> 2, sub = c & 3;
            uint32_t dst = (uint32_t)__cvta_generic_to_shared(
                &Bs[row * PAD + sub * 8]);
            const void* src = &g_St[(size_t)(j0 + row) * NCH + k0 + sub * 8];
            asm volatile("cp.async.cg.shared.global [%0], [%1], 16;"
                         :: "r"(dst), "l"(src));
        }
    }
    asm volatile("cp.async.commit_group;" ::: "memory");
}

__global__ void __launch_bounds__(256, 1) k_gemm_argmax() {
    extern __shared__ char smem[];
    __shared__ float s_inv[BN];

    const int t = threadIdx.x, lane = t & 31, warp = t >> 5;
    const int wm = warp >> 2;          // 0..1  -> 64-row slice
    const int wn = warp & 3;           // 0..3  -> 64-col slice
    const int i0 = blockIdx.y * BM;
    const int j0 = blockIdx.x * BN;

    s_inv[t] = g_inv_bn[j0 + t];       // BN == blockDim

    float acc[4][8][4];
    #pragma unroll
    for (int a = 0; a < 4; a++)
        #pragma unroll
        for (int b = 0; b < 8; b++)
            #pragma unroll
            for (int e = 0; e < 4; e++) acc[a][b][e] = 0.f;

    // ldmatrix lane addressing
    const int a_lrow = lane & 15;            // A: rows 0..15
    const int a_lcol = (lane >> 4) << 3;     // lanes 16-31 -> k+8
    const int b_lrow = lane & 7;             // B: n-row within 8
    const int b_tile = (lane >> 4) & 1;      // lanes 16-31 -> second n-tile
    const int b_lcol = ((lane >> 3) & 1) << 3;

    load_stage(smem, 0, 0, i0, j0, t);
    load_stage(smem, 1, BK, i0, j0, t);

    for (int kt = 0; kt < KT; kt++) {
        if (kt < KT - 1) asm volatile("cp.async.wait_group 1;" ::: "memory");
        else             asm volatile("cp.async.wait_group 0;" ::: "memory");
        __syncthreads();
        if (kt + 2 < KT)
            load_stage(smem, (kt + 2) % NSTAGES, (kt + 2) * BK, i0, j0, t);

        const __nv_bfloat16* As =
            (const __nv_bfloat16*)(smem + (kt % NSTAGES) * STAGE_BYTES);
        const __nv_bfloat16* Bs = As + A_STAGE_ELE;

        #pragma unroll
        for (int kk = 0; kk < 2; kk++) {
            uint32_t af[4][4];
            #pragma unroll
            for (int mt = 0; mt < 4; mt++) {
                uint32_t addr = (uint32_t)__cvta_generic_to_shared(
                    &As[(wm * 64 + mt * 16 + a_lrow) * PAD + kk * 16 + a_lcol]);
                asm volatile(
                    "ldmatrix.sync.aligned.m8n8.x4.shared.b16 {%0,%1,%2,%3}, [%4];"
                    : "=r"(af[mt][0]), "=r"(af[mt][1]), "=r"(af[mt][2]), "=r"(af[mt][3])
                    : "r"(addr));
            }
            uint32_t bf[8][2];
            #pragma unroll
            for (int np = 0; np < 4; np++) {     // pair of n-tiles per x4
                uint32_t addr = (uint32_t)__cvta_generic_to_shared(
                    &Bs[(wn * 64 + np * 16 + b_tile * 8 + b_lrow) * PAD +
                        kk * 16 + b_lcol]);
                asm volatile(
                    "ldmatrix.sync.aligned.m8n8.x4.shared.b16 {%0,%1,%2,%3}, [%4];"
                    : "=r"(bf[np * 2][0]), "=r"(bf[np * 2][1]),
                      "=r"(bf[np * 2 + 1][0]), "=r"(bf[np * 2 + 1][1])
                    : "r"(addr));
            }
            #pragma unroll
            for (int mt = 0; mt < 4; mt++)
                #pragma unroll
                for (int nt = 0; nt < 8; nt++)
                    asm volatile(
                        "mma.sync.aligned.m16n8k16.row.col.f32.bf16.bf16.f32 "
                        "{%0,%1,%2,%3}, {%4,%5,%6,%7}, {%8,%9}, {%0,%1,%2,%3};"
                        : "+f"(acc[mt][nt][0]), "+f"(acc[mt][nt][1]),
                          "+f"(acc[mt][nt][2]), "+f"(acc[mt][nt][3])
                        : "r"(af[mt][0]), "r"(af[mt][1]), "r"(af[mt][2]), "r"(af[mt][3]),
                          "r"(bf[nt][0]), "r"(bf[nt][1]));
        }
    }

    // ---- epilogue: scale by inv_bn[j], per-row argmax, atomic merge ----
    #pragma unroll
    for (int mt = 0; mt < 4; mt++) {
        #pragma unroll
        for (int rh = 0; rh < 2; rh++) {
            int row = i0 + wm * 64 + mt * 16 + rh * 8 + (lane >> 2);
            float bv = -3.4e38f;
            int   bj = 0;
            #pragma unroll
            for (int nt = 0; nt < 8; nt++) {
                #pragma unroll
                for (int e = 0; e < 2; e++) {
                    int cl = wn * 64 + nt * 8 + (lane & 3) * 2 + e;
                    float v = acc[mt][nt][rh * 2 + e] * s_inv[cl];
                    if (v > bv) { bv = v; bj = j0 + cl; }   // ascending j: first-min ties
                }
            }
            #pragma unroll
            for (int o = 1; o < 4; o <<= 1) {
                float ov = __shfl_xor_sync(0xffffffffu, bv, o);
                int   oj = __shfl_xor_sync(0xffffffffu, bj, o);
                if (ov > bv || (ov == bv && oj < bj)) { bv = ov; bj = oj; }
            }
            if ((lane & 3) == 0) {
                unsigned int u = __float_as_uint(bv);
                u = (u & 0x80000000u) ? ~u : (u | 0x80000000u);
                unsigned long long p =
                    ((unsigned long long)u << 32) | (unsigned int)(~(unsigned)bj);
                atomicMax(&g_best[row], p);
            }
        }
    }
}

// ---------------- cos loss: warp per pixel, bf16 rows, fp32 accum ----------------
__global__ void k_cos() {
    int gw = (blockIdx.x * 256 + threadIdx.x) >> 5;   // global warp id = pixel i
    int lane = threadIdx.x & 31;
    if (gw >= NPIX) return;
    unsigned long long p = g_best[gw];
    int j = (int)(~(unsigned int)(p & 0xFFFFFFFFull));

    const uint4* xr = (const uint4*)&g_Xt[(size_t)gw * NCH];   // 96 uint4 per row
    const uint4* sr = (const uint4*)&g_St[(size_t)j * NCH];
    float dot = 0.f;
    #pragma unroll
    for (int u = lane; u < 96; u += 32) {
        uint4 a = xr[u], b = sr[u];
        const __nv_bfloat162* ah = (const __nv_bfloat162*)&a;
        const __nv_bfloat162* bh = (const __nv_bfloat162*)&b;
        #pragma unroll
        for (int q = 0; q < 4; q++) {
            float2 fa = __bfloat1622float2(ah[q]);
            float2 fb = __bfloat1622float2(bh[q]);
            dot += fa.x * fb.x + fa.y * fb.y;
        }
    }
    #pragma unroll
    for (int o = 16; o > 0; o >>= 1)
        dot += __shfl_xor_sync(0xffffffffu, dot, o);
    if (lane == 0) {
        float cs = dot / ((sqrtf(g_sx[gw]) + EPSF) * (sqrtf(g_ss[j]) + EPSF));
        g_loss[gw] = 1.0f - cs;
    }
}

// ---------------- deterministic final reduction ----------------
__global__ void k_reduce(float* __restrict__ out) {
    __shared__ float sm[256];
    float sum = 0.f;
    for (int i = threadIdx.x; i < NPIX; i += 256) sum += g_loss[i];
    sm[threadIdx.x] = sum;
    __syncthreads();
    for (int o = 128; o > 0; o >>= 1) {
        if (threadIdx.x < o) sm[threadIdx.x] += sm[threadIdx.x + o];
        __syncthreads();
    }
    if (threadIdx.x == 0) out[0] = sm[0] / (float)NPIX;
}

// ---------------- launch ----------------
extern "C" void kernel_launch(void* const* d_in, const int* in_sizes, int n_in,
                              void* d_out, int out_size) {
    const float* x = (const float*)d_in[0];
    const float* s = (const float*)d_in[1];
    float* out = (float*)d_out;

    cudaFuncSetAttribute(k_gemm_argmax,
                         cudaFuncAttributeMaxDynamicSharedMemorySize, SMEM_TOTAL);

    dim3 tb(32, 32);
    dim3 tg(NPIX / 32, NCH / 32);
    k_transpose<<<tg, tb>>>(x, 0);
    k_transpose<<<tg, tb>>>(s, 1);
    k_norms<<<NPIX / 256, 256>>>(x, s);
    k_gemm_argmax<<<dim3(NPIX / BN, NPIX / BM), 256, SMEM_TOTAL>>>();
    k_cos<<<(NPIX * 32 + 255) / 256, 256>>>();
    k_reduce<<<1, 256>>>(out);
}

// round 4
// speedup vs baseline: 1.3565x; 1.1147x over previous
#include <cuda_runtime.h>
#include <cuda_bf16.h>
#include <cstdint>

#define NPIX 12544          // 112*112 = 98*128
#define NCH  768
#define EPSF 1e-8f

// ---- GEMM tile config (legacy mma.sync path; tcgen05 not reachable on compute_103) ----
#define BM 128
#define BN 128
#define BK 32
#define KT (NCH / BK)       // 24 k-tiles
#define NSTAGES 4
#define PAD 40              // bf16 elems per smem row (80B pitch -> conflict-free ldmatrix)

#define A_STAGE_ELE (BM * PAD)
#define B_STAGE_ELE (BN * PAD)
#define STAGE_ELE   (A_STAGE_ELE + B_STAGE_ELE)
#define STAGE_BYTES (STAGE_ELE * 2)                  // 20480
#define SMEM_TOTAL  (NSTAGES * STAGE_BYTES)          // 81920 -> 2 CTAs/SM fit in 228KB

// ---------------- scratch (no allocations allowed) ----------------
__device__ __nv_bfloat16 g_Xt[(size_t)NPIX * NCH];   // [pixel][channel] bf16
__device__ __nv_bfloat16 g_St[(size_t)NPIX * NCH];
__device__ float g_sx[NPIX];
__device__ float g_ss[NPIX];
__device__ float g_inv_bn[NPIX];
__device__ unsigned long long g_best[NPIX];
__device__ float g_loss[NPIX];

// ---------------- transpose + fp32 -> bf16 convert ----------------
__global__ void k_transpose(const float* __restrict__ src, int dst_sel) {
    __shared__ float tile[32][33];
    __nv_bfloat16* dst = dst_sel ? g_St : g_Xt;
    int i0 = blockIdx.x * 32;
    int c0 = blockIdx.y * 32;
    tile[threadIdx.y][threadIdx.x] =
        src[(size_t)(c0 + threadIdx.y) * NPIX + i0 + threadIdx.x];
    __syncthreads();
    dst[(size_t)(i0 + threadIdx.y) * NCH + c0 + threadIdx.x] =
        __float2bfloat16(tile[threadIdx.x][threadIdx.y]);
}

// ---------------- per-pixel norms (exact fp32, coalesced) ----------------
__global__ void k_norms(const float* __restrict__ x, const float* __restrict__ s) {
    int i = blockIdx.x * 256 + threadIdx.x;
    if (i >= NPIX) return;
    float sx = 0.f, ss = 0.f;
    for (int c = 0; c < NCH; c++) {
        float a = x[(size_t)c * NPIX + i]; sx += a * a;
        float b = s[(size_t)c * NPIX + i]; ss += b * b;
    }
    g_sx[i] = sx;
    g_ss[i] = ss;
    g_inv_bn[i] = 1.0f / (sqrtf(ss + EPSF) + EPSF);
    g_best[i] = 0ull;
}

// ---------------- GEMM stage loader: 1024 x 16B chunks, 4 per thread ----------------
__device__ __forceinline__ void load_stage(char* smem, int stage, int k0,
                                           int i0, int j0, int t) {
    __nv_bfloat16* As = (__nv_bfloat16*)(smem + stage * STAGE_BYTES);
    __nv_bfloat16* Bs = As + A_STAGE_ELE;
    #pragma unroll
    for (int u = 0; u < 4; u++) {
        int chunk = t + u * 256;                 // 0..1023
        int row = (chunk >> 2) & 127;
        int sub = chunk & 3;
        if (chunk < 512) {                       // A: 128 rows x 4 chunks
            uint32_t dst = (uint32_t)__cvta_generic_to_shared(
                &As[row * PAD + sub * 8]);
            const void* src = &g_Xt[(size_t)(i0 + row) * NCH + k0 + sub * 8];
            asm volatile("cp.async.cg.shared.global [%0], [%1], 16;"
                         :: "r"(dst), "l"(src));
        } else {                                 // B: 128 rows x 4 chunks
            uint32_t dst = (uint32_t)__cvta_generic_to_shared(
                &Bs[row * PAD + sub * 8]);
            const void* src = &g_St[(size_t)(j0 + row) * NCH + k0 + sub * 8];
            asm volatile("cp.async.cg.shared.global [%0], [%1], 16;"
                         :: "r"(dst), "l"(src));
        }
    }
    asm volatile("cp.async.commit_group;" ::: "memory");
}

// ---------------- GEMM (mma.sync bf16) + fused per-row argmax ----------------
__global__ void __launch_bounds__(256, 2) k_gemm_argmax() {
    extern __shared__ char smem[];
    __shared__ float s_inv[BN];

    const int t = threadIdx.x, lane = t & 31, warp = t >> 5;
    const int wm = warp >> 2;          // 0..1  -> 64-row slice
    const int wn = warp & 3;           // 0..3  -> 32-col slice
    const int i0 = blockIdx.y * BM;
    const int j0 = blockIdx.x * BN;

    if (t < BN) s_inv[t] = g_inv_bn[j0 + t];

    float acc[4][4][4];
    #pragma unroll
    for (int a = 0; a < 4; a++)
        #pragma unroll
        for (int b = 0; b < 4; b++)
            #pragma unroll
            for (int e = 0; e < 4; e++) acc[a][b][e] = 0.f;

    // ldmatrix lane addressing
    const int a_lrow = lane & 15;            // A x4: rows 0..15
    const int a_lcol = (lane >> 4) << 3;     // lanes 16-31 -> k+8
    const int b_lrow = lane & 7;             // B x4: n-row within 8
    const int b_tile = (lane >> 4) & 1;      // lanes 16-31 -> +8 n
    const int b_lcol = ((lane >> 3) & 1) << 3;

    load_stage(smem, 0, 0, i0, j0, t);
    load_stage(smem, 1, BK, i0, j0, t);
    load_stage(smem, 2, 2 * BK, i0, j0, t);

    for (int kt = 0; kt < KT; kt++) {
        if (kt < KT - 2)      asm volatile("cp.async.wait_group 2;" ::: "memory");
        else if (kt == KT - 2) asm volatile("cp.async.wait_group 1;" ::: "memory");
        else                  asm volatile("cp.async.wait_group 0;" ::: "memory");
        __syncthreads();
        if (kt + 3 < KT)
            load_stage(smem, (kt + 3) % NSTAGES, (kt + 3) * BK, i0, j0, t);

        const __nv_bfloat16* As =
            (const __nv_bfloat16*)(smem + (kt % NSTAGES) * STAGE_BYTES);
        const __nv_bfloat16* Bs = As + A_STAGE_ELE;

        #pragma unroll
        for (int kk = 0; kk < 2; kk++) {
            uint32_t af[4][4];
            #pragma unroll
            for (int mt = 0; mt < 4; mt++) {
                uint32_t addr = (uint32_t)__cvta_generic_to_shared(
                    &As[(wm * 64 + mt * 16 + a_lrow) * PAD + kk * 16 + a_lcol]);
                asm volatile(
                    "ldmatrix.sync.aligned.m8n8.x4.shared.b16 {%0,%1,%2,%3}, [%4];"
                    : "=r"(af[mt][0]), "=r"(af[mt][1]), "=r"(af[mt][2]), "=r"(af[mt][3])
                    : "r"(addr));
            }
            uint32_t bf[4][2];
            #pragma unroll
            for (int np = 0; np < 2; np++) {     // each x4 covers 2 n-tiles (16 cols)
                uint32_t addr = (uint32_t)__cvta_generic_to_shared(
                    &Bs[(wn * 32 + np * 16 + b_tile * 8 + b_lrow) * PAD +
                        kk * 16 + b_lcol]);
                asm volatile(
                    "ldmatrix.sync.aligned.m8n8.x4.shared.b16 {%0,%1,%2,%3}, [%4];"
                    : "=r"(bf[np * 2][0]), "=r"(bf[np * 2][1]),
                      "=r"(bf[np * 2 + 1][0]), "=r"(bf[np * 2 + 1][1])
                    : "r"(addr));
            }
            #pragma unroll
            for (int mt = 0; mt < 4; mt++)
                #pragma unroll
                for (int nt = 0; nt < 4; nt++)
                    asm volatile(
                        "mma.sync.aligned.m16n8k16.row.col.f32.bf16.bf16.f32 "
                        "{%0,%1,%2,%3}, {%4,%5,%6,%7}, {%8,%9}, {%0,%1,%2,%3};"
                        : "+f"(acc[mt][nt][0]), "+f"(acc[mt][nt][1]),
                          "+f"(acc[mt][nt][2]), "+f"(acc[mt][nt][3])
                        : "r"(af[mt][0]), "r"(af[mt][1]), "r"(af[mt][2]), "r"(af[mt][3]),
                          "r"(bf[nt][0]), "r"(bf[nt][1]));
        }
    }

    // ---- epilogue: scale by inv_bn[j], per-row argmax, atomic merge ----
    #pragma unroll
    for (int mt = 0; mt < 4; mt++) {
        #pragma unroll
        for (int rh = 0; rh < 2; rh++) {
            int row = i0 + wm * 64 + mt * 16 + rh * 8 + (lane >> 2);
            float bv = -3.4e38f;
            int   bj = 0;
            #pragma unroll
            for (int nt = 0; nt < 4; nt++) {
                #pragma unroll
                for (int e = 0; e < 2; e++) {
                    int cl = wn * 32 + nt * 8 + (lane & 3) * 2 + e;
                    float v = acc[mt][nt][rh * 2 + e] * s_inv[cl];
                    if (v > bv) { bv = v; bj = j0 + cl; }   // ascending j: first-min ties
                }
            }
            #pragma unroll
            for (int o = 1; o < 4; o <<= 1) {
                float ov = __shfl_xor_sync(0xffffffffu, bv, o);
                int   oj = __shfl_xor_sync(0xffffffffu, bj, o);
                if (ov > bv || (ov == bv && oj < bj)) { bv = ov; bj = oj; }
            }
            if ((lane & 3) == 0) {
                unsigned int u = __float_as_uint(bv);
                u = (u & 0x80000000u) ? ~u : (u | 0x80000000u);
                unsigned long long p =
                    ((unsigned long long)u << 32) | (unsigned int)(~(unsigned)bj);
                atomicMax(&g_best[row], p);
            }
        }
    }
}

// ---------------- cos loss: warp per pixel, bf16 rows, fp32 accum ----------------
__global__ void k_cos() {
    int gw = (blockIdx.x * 256 + threadIdx.x) >> 5;   // global warp id = pixel i
    int lane = threadIdx.x & 31;
    if (gw >= NPIX) return;
    unsigned long long p = g_best[gw];
    int j = (int)(~(unsigned int)(p & 0xFFFFFFFFull));

    const uint4* xr = (const uint4*)&g_Xt[(size_t)gw * NCH];   // 96 uint4 per row
    const uint4* sr = (const uint4*)&g_St[(size_t)j * NCH];
    float dot = 0.f;
    #pragma unroll
    for (int u = lane; u < 96; u += 32) {
        uint4 a = xr[u], b = sr[u];
        const __nv_bfloat162* ah = (const __nv_bfloat162*)&a;
        const __nv_bfloat162* bh = (const __nv_bfloat162*)&b;
        #pragma unroll
        for (int q = 0; q < 4; q++) {
            float2 fa = __bfloat1622float2(ah[q]);
            float2 fb = __bfloat1622float2(bh[q]);
            dot += fa.x * fb.x + fa.y * fb.y;
        }
    }
    #pragma unroll
    for (int o = 16; o > 0; o >>= 1)
        dot += __shfl_xor_sync(0xffffffffu, dot, o);
    if (lane == 0) {
        float cs = dot / ((sqrtf(g_sx[gw]) + EPSF) * (sqrtf(g_ss[j]) + EPSF));
        g_loss[gw] = 1.0f - cs;
    }
}

// ---------------- deterministic final reduction ----------------
__global__ void k_reduce(float* __restrict__ out) {
    __shared__ float sm[256];
    float sum = 0.f;
    for (int i = threadIdx.x; i < NPIX; i += 256) sum += g_loss[i];
    sm[threadIdx.x] = sum;
    __syncthreads();
    for (int o = 128; o > 0; o >>= 1) {
        if (threadIdx.x < o) sm[threadIdx.x] += sm[threadIdx.x + o];
        __syncthreads();
    }
    if (threadIdx.x == 0) out[0] = sm[0] / (float)NPIX;
}

// ---------------- launch ----------------
extern "C" void kernel_launch(void* const* d_in, const int* in_sizes, int n_in,
                              void* d_out, int out_size) {
    const float* x = (const float*)d_in[0];
    const float* s = (const float*)d_in[1];
    float* out = (float*)d_out;

    cudaFuncSetAttribute(k_gemm_argmax,
                         cudaFuncAttributeMaxDynamicSharedMemorySize, SMEM_TOTAL);

    dim3 tb(32, 32);
    dim3 tg(NPIX / 32, NCH / 32);
    k_transpose<<<tg, tb>>>(x, 0);
    k_transpose<<<tg, tb>>>(s, 1);
    k_norms<<<NPIX / 256, 256>>>(x, s);
    k_gemm_argmax<<<dim3(NPIX / BN, NPIX / BM), 256, SMEM_TOTAL>>>();
    k_cos<<<(NPIX * 32 + 255) / 256, 256>>>();
    k_reduce<<<1, 256>>>(out);
}

// round 6
// speedup vs baseline: 1.5454x; 1.1393x over previous
#include <cuda_runtime.h>
#include <cuda_bf16.h>
#include <cstdint>

#define NPIX 12544          // 112*112 = 98*128
#define NCH  768
#define EPSF 1e-8f

// ---- GEMM tile config (legacy mma.sync; tcgen05 not reachable on compute_103) ----
#define BM 128
#define BN 128
#define BK 64
#define KT (NCH / BK)       // 12 k-tiles
#define NSTAGES 3
#define PAD 72              // 64 + 8 bf16 elems per row (144B pitch, conflict-free)

#define A_STAGE_ELE (BM * PAD)
#define B_STAGE_ELE (BN * PAD)
#define STAGE_ELE   (A_STAGE_ELE + B_STAGE_ELE)
#define STAGE_BYTES (STAGE_ELE * 2)                  // 36864
#define SMEM_TOTAL  (NSTAGES * STAGE_BYTES)          // 110592 -> 2 CTAs/SM

// ---------------- scratch (no allocations allowed) ----------------
__device__ __nv_bfloat16 g_Xt[(size_t)NPIX * NCH];   // [pixel][channel] bf16
__device__ __nv_bfloat16 g_St[(size_t)NPIX * NCH];
__device__ float g_sx[NPIX];
__device__ float g_ss[NPIX];
__device__ float g_inv_bn[NPIX];
__device__ unsigned long long g_best[NPIX];
__device__ float g_loss[NPIX];

// ---------------- transpose + fp32 -> bf16 convert ----------------
__global__ void k_transpose(const float* __restrict__ src, int dst_sel) {
    __shared__ float tile[32][33];
    __nv_bfloat16* dst = dst_sel ? g_St : g_Xt;
    int i0 = blockIdx.x * 32;
    int c0 = blockIdx.y * 32;
    tile[threadIdx.y][threadIdx.x] =
        src[(size_t)(c0 + threadIdx.y) * NPIX + i0 + threadIdx.x];
    __syncthreads();
    dst[(size_t)(i0 + threadIdx.y) * NCH + c0 + threadIdx.x] =
        __float2bfloat16(tile[threadIdx.x][threadIdx.y]);
}

// ---------------- per-pixel norms (exact fp32, coalesced) ----------------
__global__ void k_norms(const float* __restrict__ x, const float* __restrict__ s) {
    int i = blockIdx.x * 256 + threadIdx.x;
    if (i >= NPIX) return;
    float sx = 0.f, ss = 0.f;
    for (int c = 0; c < NCH; c++) {
        float a = x[(size_t)c * NPIX + i]; sx += a * a;
        float b = s[(size_t)c * NPIX + i]; ss += b * b;
    }
    g_sx[i] = sx;
    g_ss[i] = ss;
    g_inv_bn[i] = 1.0f / (sqrtf(ss + EPSF) + EPSF);
    g_best[i] = 0ull;
}

// ---------------- stage loader: 2048 x 16B chunks, 8 per thread ----------------
__device__ __forceinline__ void load_stage(char* smem, int stage, int k0,
                                           int i0, int j0, int t) {
    __nv_bfloat16* As = (__nv_bfloat16*)(smem + stage * STAGE_BYTES);
    __nv_bfloat16* Bs = As + A_STAGE_ELE;
    #pragma unroll
    for (int u = 0; u < 8; u++) {
        int chunk = t + u * 256;                 // 0..2047
        int row = (chunk >> 3) & 127;
        int sub = chunk & 7;
        if (chunk < 1024) {                      // A: 128 rows x 8 chunks
            uint32_t dst = (uint32_t)__cvta_generic_to_shared(
                &As[row * PAD + sub * 8]);
            const void* src = &g_Xt[(size_t)(i0 + row) * NCH + k0 + sub * 8];
            asm volatile("cp.async.cg.shared.global [%0], [%1], 16;"
                         :: "r"(dst), "l"(src));
        } else {                                 // B: 128 rows x 8 chunks
            uint32_t dst = (uint32_t)__cvta_generic_to_shared(
                &Bs[row * PAD + sub * 8]);
            const void* src = &g_St[(size_t)(j0 + row) * NCH + k0 + sub * 8];
            asm volatile("cp.async.cg.shared.global [%0], [%1], 16;"
                         :: "r"(dst), "l"(src));
        }
    }
    asm volatile("cp.async.commit_group;" ::: "memory");
}

// ---------------- GEMM (mma.sync bf16) + fused per-row argmax ----------------
__global__ void __launch_bounds__(256, 2) k_gemm_argmax() {
    extern __shared__ char smem[];
    __shared__ float s_inv[BN];

    const int t = threadIdx.x, lane = t & 31, warp = t >> 5;
    const int wm = warp >> 2;          // 0..1  -> 64-row slice
    const int wn = warp & 3;           // 0..3  -> 32-col slice
    const int i0 = blockIdx.y * BM;
    const int j0 = blockIdx.x * BN;

    if (t < BN) s_inv[t] = g_inv_bn[j0 + t];

    float acc[4][4][4];
    #pragma unroll
    for (int a = 0; a < 4; a++)
        #pragma unroll
        for (int b = 0; b < 4; b++)
            #pragma unroll
            for (int e = 0; e < 4; e++) acc[a][b][e] = 0.f;

    // precomputed per-warp ldmatrix byte offsets (relative to stage base)
    const int a_lrow = lane & 15;
    const int a_lcol = (lane >> 4) << 3;
    const int b_lrow = lane & 7;
    const int b_tile = (lane >> 4) & 1;
    const int b_lcol = ((lane >> 3) & 1) << 3;
    uint32_t a_off[4], b_off[2];
    #pragma unroll
    for (int mt = 0; mt < 4; mt++)
        a_off[mt] = ((wm * 64 + mt * 16 + a_lrow) * PAD + a_lcol) * 2;
    #pragma unroll
    for (int np = 0; np < 2; np++)
        b_off[np] = (A_STAGE_ELE +
                     (wn * 32 + np * 16 + b_tile * 8 + b_lrow) * PAD + b_lcol) * 2;
    const uint32_t smem_base = (uint32_t)__cvta_generic_to_shared(smem);

    load_stage(smem, 0, 0, i0, j0, t);
    load_stage(smem, 1, BK, i0, j0, t);

    for (int kt = 0; kt < KT; kt++) {
        if (kt < KT - 1) asm volatile("cp.async.wait_group 1;" ::: "memory");
        else             asm volatile("cp.async.wait_group 0;" ::: "memory");
        __syncthreads();
        if (kt + 2 < KT)
            load_stage(smem, (kt + 2) % NSTAGES, (kt + 2) * BK, i0, j0, t);

        const uint32_t stage_base = smem_base + (kt % NSTAGES) * STAGE_BYTES;

        #pragma unroll
        for (int kk = 0; kk < 4; kk++) {
            const uint32_t koff = kk * 32;       // 16 bf16 = 32 bytes per kk step
            uint32_t af[4][4];
            #pragma unroll
            for (int mt = 0; mt < 4; mt++)
                asm volatile(
                    "ldmatrix.sync.aligned.m8n8.x4.shared.b16 {%0,%1,%2,%3}, [%4];"
                    : "=r"(af[mt][0]), "=r"(af[mt][1]), "=r"(af[mt][2]), "=r"(af[mt][3])
                    : "r"(stage_base + a_off[mt] + koff));
            uint32_t bf[4][2];
            #pragma unroll
            for (int np = 0; np < 2; np++)
                asm volatile(
                    "ldmatrix.sync.aligned.m8n8.x4.shared.b16 {%0,%1,%2,%3}, [%4];"
                    : "=r"(bf[np * 2][0]), "=r"(bf[np * 2][1]),
                      "=r"(bf[np * 2 + 1][0]), "=r"(bf[np * 2 + 1][1])
                    : "r"(stage_base + b_off[np] + koff));
            #pragma unroll
            for (int mt = 0; mt < 4; mt++)
                #pragma unroll
                for (int nt = 0; nt < 4; nt++)
                    asm volatile(
                        "mma.sync.aligned.m16n8k16.row.col.f32.bf16.bf16.f32 "
                        "{%0,%1,%2,%3}, {%4,%5,%6,%7}, {%8,%9}, {%0,%1,%2,%3};"
                        : "+f"(acc[mt][nt][0]), "+f"(acc[mt][nt][1]),
                          "+f"(acc[mt][nt][2]), "+f"(acc[mt][nt][3])
                        : "r"(af[mt][0]), "r"(af[mt][1]), "r"(af[mt][2]), "r"(af[mt][3]),
                          "r"(bf[nt][0]), "r"(bf[nt][1]));
        }
    }

    // ---- epilogue: scale by inv_bn[j], per-row argmax, atomic merge ----
    #pragma unroll
    for (int mt = 0; mt < 4; mt++) {
        #pragma unroll
        for (int rh = 0; rh < 2; rh++) {
            int row = i0 + wm * 64 + mt * 16 + rh * 8 + (lane >> 2);
            float bv = -3.4e38f;
            int   bj = 0;
            #pragma unroll
            for (int nt = 0; nt < 4; nt++) {
                #pragma unroll
                for (int e = 0; e < 2; e++) {
                    int cl = wn * 32 + nt * 8 + (lane & 3) * 2 + e;
                    float v = acc[mt][nt][rh * 2 + e] * s_inv[cl];
                    if (v > bv) { bv = v; bj = j0 + cl; }   // ascending j: first-min ties
                }
            }
            #pragma unroll
            for (int o = 1; o < 4; o <<= 1) {
                float ov = __shfl_xor_sync(0xffffffffu, bv, o);
                int   oj = __shfl_xor_sync(0xffffffffu, bj, o);
                if (ov > bv || (ov == bv && oj < bj)) { bv = ov; bj = oj; }
            }
            if ((lane & 3) == 0) {
                unsigned int u = __float_as_uint(bv);
                u = (u & 0x80000000u) ? ~u : (u | 0x80000000u);
                unsigned long long p =
                    ((unsigned long long)u << 32) | (unsigned int)(~(unsigned)bj);
                atomicMax(&g_best[row], p);
            }
        }
    }
}

// ---------------- cos loss: warp per pixel, bf16 rows, fp32 accum ----------------
__global__ void k_cos() {
    int gw = (blockIdx.x * 256 + threadIdx.x) >> 5;
    int lane = threadIdx.x & 31;
    if (gw >= NPIX) return;
    unsigned long long p = g_best[gw];
    int j = (int)(~(unsigned int)(p & 0xFFFFFFFFull));

    const uint4* xr = (const uint4*)&g_Xt[(size_t)gw * NCH];
    const uint4* sr = (const uint4*)&g_St[(size_t)j * NCH];
    float dot = 0.f;
    #pragma unroll
    for (int u = lane; u < 96; u += 32) {
        uint4 a = xr[u], b = sr[u];
        const __nv_bfloat162* ah = (const __nv_bfloat162*)&a;
        const __nv_bfloat162* bh = (const __nv_bfloat162*)&b;
        #pragma unroll
        for (int q = 0; q < 4; q++) {
            float2 fa = __bfloat1622float2(ah[q]);
            float2 fb = __bfloat1622float2(bh[q]);
            dot += fa.x * fb.x + fa.y * fb.y;
        }
    }
    #pragma unroll
    for (int o = 16; o > 0; o >>= 1)
        dot += __shfl_xor_sync(0xffffffffu, dot, o);
    if (lane == 0) {
        float cs = dot / ((sqrtf(g_sx[gw]) + EPSF) * (sqrtf(g_ss[j]) + EPSF));
        g_loss[gw] = 1.0f - cs;
    }
}

// ---------------- deterministic final reduction ----------------
__global__ void k_reduce(float* __restrict__ out) {
    __shared__ float sm[256];
    float sum = 0.f;
    for (int i = threadIdx.x; i < NPIX; i += 256) sum += g_loss[i];
    sm[threadIdx.x] = sum;
    __syncthreads();
    for (int o = 128; o > 0; o >>= 1) {
        if (threadIdx.x < o) sm[threadIdx.x] += sm[threadIdx.x + o];
        __syncthreads();
    }
    if (threadIdx.x == 0) out[0] = sm[0] / (float)NPIX;
}

// ---------------- launch ----------------
extern "C" void kernel_launch(void* const* d_in, const int* in_sizes, int n_in,
                              void* d_out, int out_size) {
    const float* x = (const float*)d_in[0];
    const float* s = (const float*)d_in[1];
    float* out = (float*)d_out;

    cudaFuncSetAttribute(k_gemm_argmax,
                         cudaFuncAttributeMaxDynamicSharedMemorySize, SMEM_TOTAL);

    dim3 tb(32, 32);
    dim3 tg(NPIX / 32, NCH / 32);
    k_transpose<<<tg, tb>>>(x, 0);
    k_transpose<<<tg, tb>>>(s, 1);
    k_norms<<<NPIX / 256, 256>>>(x, s);
    k_gemm_argmax<<<dim3(NPIX / BN, NPIX / BM), 256, SMEM_TOTAL>>>();
    k_cos<<<(NPIX * 32 + 255) / 256, 256>>>();
    k_reduce<<<1, 256>>>(out);
}